// round 3
// baseline (speedup 1.0000x reference)
#include <cuda_runtime.h>
#include <math.h>

#define TT     4096
#define BB     9
#define KP     512
#define NA     48
#define NB     96
#define GRIDN  (NA + NB + 1)
#define NTHR   384
#define NTICKS 4100
#define PB     12
#define SMEMB  ((6144 * 3 + 512) * 4)

__device__ float    g_h1[2][KP * PB];
__device__ float    g_h2[2][KP * PB];
__device__ float    g_mr[8][BB * 8];
__device__ unsigned g_bar;

__device__ __forceinline__ void gridbar(unsigned target) {
    __syncthreads();
    if (threadIdx.x == 0) {
        __threadfence();
        atomicAdd(&g_bar, 1u);
        volatile unsigned* p = &g_bar;
        while (*p < target) { }
        __threadfence();
    }
    __syncthreads();
}

__device__ __forceinline__ void stage6144(float* dst, const float* src) {
    const float4* s = (const float4*)src;
    float4*       d = (float4*)dst;
    for (int i = threadIdx.x; i < (KP * PB) / 4; i += NTHR) d[i] = __ldcg(s + i);
}

__device__ __forceinline__ void wred(float* a, int n) {
    for (int o = 16; o; o >>= 1)
        for (int j = 0; j < n; j++) a[j] += __shfl_xor_sync(0xffffffffu, a[j], o);
}

__device__ __forceinline__ void rowdot9(const float* wrow, const float* x,
                                        float* acc, int lane) {
    #pragma unroll 4
    for (int k = lane; k < KP; k += 32) {
        float w = wrow[k];
        const float* xp = x + k * PB;
        float4 a = *(const float4*)(xp);
        float4 b = *(const float4*)(xp + 4);
        float  c = xp[8];
        acc[0] += w * a.x; acc[1] += w * a.y; acc[2] += w * a.z; acc[3] += w * a.w;
        acc[4] += w * b.x; acc[5] += w * b.y; acc[6] += w * b.z; acc[7] += w * b.w;
        acc[8] += w * c;
    }
}

// AUX offsets. role A: Win 0..143, bin 160..175, net_in 176..287
//              role B: bout 0..15, partials 16..124
//              role C: js 0..35, m_prev 40..95, M_arm 100..111

__global__ void __launch_bounds__(NTHR, 1)
ctrl_kernel(const float* __restrict__ pert,
            const float* __restrict__ n1g,  const float* __restrict__ n2g,
            const float* __restrict__ nmg,  const float* __restrict__ home,
            const float* __restrict__ Win,  const float* __restrict__ bin,
            const float* __restrict__ Wsf1, const float* __restrict__ Wout,
            const float* __restrict__ bout, const float* __restrict__ Wsf2,
            const float* __restrict__ Wmus, const float* __restrict__ Marm,
            float* __restrict__ out)
{
    extern __shared__ float sm[];
    float* X0  = sm;
    float* X1  = sm + 6144;
    float* W   = sm + 12288;
    float* AUX = sm + 18432;

    const int tid  = threadIdx.x;
    const int lane = tid & 31;
    const int wrp  = tid >> 5;
    const int bid  = blockIdx.x;
    const int role = (bid < NA) ? 0 : (bid < NA + NB ? 1 : 2);
    int r0 = 0, R = 0;

    // ---- preload weights into SMEM (once) ----
    if (role == 0) {
        r0 = (bid * 500) / NA;
        R  = ((bid + 1) * 500) / NA - r0;
        for (int i = tid; i < R * KP; i += NTHR) {
            int w = i / KP, k = i % KP;
            W[i] = (k < 500) ? Wsf1[(r0 + w) * 500 + k] : 0.f;
        }
        for (int i = tid; i < R * 12; i += NTHR)
            AUX[i] = Win[(r0 + i / 12) * 12 + (i % 12)];
        if (tid < R) AUX[160 + tid] = bin[r0 + tid];
    } else if (role == 1) {
        int b2 = bid - NA;
        r0 = (b2 * 500) / NB;
        R  = ((b2 + 1) * 500) / NB - r0;
        for (int i = tid; i < 2 * R * KP; i += NTHR) {
            int w = i / KP, k = i % KP;
            float v = 0.f;
            if (k < 500)
                v = (w < R) ? Wout[(r0 + w) * 500 + k]
                            : Wsf2[(r0 + w - R) * 500 + k];
            W[i] = v;
        }
        if (tid < R) AUX[tid] = bout[r0 + tid];
    } else {
        for (int i = tid; i < KP * 8; i += NTHR) {
            int k = i / 8, j = i % 8;
            W[i] = (k < 500 && j < 6) ? Wmus[j * 500 + k] : 0.f;
        }
        if (tid < 12) AUX[100 + tid] = Marm[tid];
    }

    unsigned tgt = GRIDN;
    gridbar(tgt); tgt += GRIDN;

    // ---- tick loop: 1 grid barrier per tick ----
    for (int tk = 0; tk < NTICKS; ++tk) {
        if (role == 0) {
            int t = (tk == 0) ? 0 : tk - 2;
            bool act = (tk == 0) || (tk >= 3 && t <= TT - 1);
            if (act) {
                if (t == 0) {
                    if (wrp < R && lane < 9)
                        g_h1[0][(r0 + wrp) * PB + lane] = tanhf(AUX[160 + wrp]);
                } else {
                    stage6144(X0, g_h1[(t - 1) & 1]);
                    if (tid < 108) {
                        int b = tid / 12, c = tid % 12;
                        int t6 = t - 6; if (t6 < 0) t6 = 0;
                        float v = 0.f;
                        if (c >= 2 && c < 6) {
                            float js = __ldcg(out + t6 * 36 + b * 4 + (c - 2));
                            v = (c < 4) ? 2.0f * (js - home[b * 2 + (c - 2)])
                                        : 0.5f * js;
                        } else if (c >= 6) {
                            v = __ldcg(&g_mr[t6 & 7][b * 8 + (c - 6)]);
                        }
                        AUX[176 + b * 12 + c] = v;
                    }
                    float nse = 0.f;
                    if (wrp < R && lane < 9)
                        nse = __ldcg(n1g + (long)(t - 1) * (BB * 500)
                                         + lane * 500 + (r0 + wrp));
                    __syncthreads();
                    if (wrp < R) {
                        float acc[9] = {0,0,0,0,0,0,0,0,0};
                        rowdot9(W + wrp * KP, X0, acc, lane);
                        wred(acc, 9);
                        if (lane < 9) {
                            int i = r0 + wrp, b = lane;
                            float pre = acc[b] + AUX[160 + wrp];
                            #pragma unroll
                            for (int c = 0; c < 12; c++)
                                pre += AUX[wrp * 12 + c] * AUX[176 + b * 12 + c];
                            float hp = X0[i * PB + b];
                            g_h1[t & 1][i * PB + b] =
                                0.5f * tanhf(pre) + 0.5f * hp + nse * hp * hp;
                        }
                    }
                }
            }
        } else if (role == 1) {
            int t = (tk == 1) ? 0 : tk - 3;
            bool act = (tk == 1) || (tk >= 4 && t <= TT - 1);
            if (act) {
                stage6144(X0, g_h1[t & 1]);
                stage6144(X1, g_h2[(t - 1) & 1]);
                float nse = 0.f;
                if (t >= 1 && tid < R * 9)
                    nse = __ldcg(n2g + (long)(t - 1) * (BB * 500)
                                     + (tid % 9) * 500 + (r0 + tid / 9));
                __syncthreads();
                if (wrp < 2 * R) {
                    float acc[9] = {0,0,0,0,0,0,0,0,0};
                    rowdot9(W + wrp * KP, (wrp < R) ? X0 : X1, acc, lane);
                    wred(acc, 9);
                    if (lane < 9) AUX[16 + wrp * 9 + lane] = acc[lane];
                }
                __syncthreads();
                if (tid < R * 9) {
                    int w = tid / 9, b = tid % 9, i = r0 + w;
                    float pre = AUX[16 + w * 9 + b] + AUX[16 + (w + R) * 9 + b]
                              + AUX[w];
                    float val;
                    if (t == 0) {
                        val = tanhf(pre);
                    } else {
                        float hp = X1[i * PB + b];
                        val = 0.5f * tanhf(pre) + 0.5f * hp + nse * hp * hp;
                    }
                    g_h2[t & 1][i * PB + b] = val;
                }
            }
        } else {
            int t = (tk == 2) ? 0 : tk - 4;
            bool act = (tk == 2) || (tk >= 5 && t <= TT - 1);
            if (act) {
                stage6144(X0, g_h2[t & 1]);
                float nse = 0.f, pse = 0.f;
                if (t >= 1 && wrp < 9) {
                    if (lane < 6)
                        nse = __ldcg(nmg + (long)(t - 1) * (BB * 6)
                                         + wrp * 6 + lane);
                    if (lane < 2)
                        pse = __ldcg(pert + (long)(t - 1) * (BB * 2)
                                          + wrp * 2 + lane);
                }
                __syncthreads();
                if (wrp < 9) {
                    int b = wrp;
                    float acc[6] = {0,0,0,0,0,0};
                    #pragma unroll 4
                    for (int k = lane; k < KP; k += 32) {
                        float xv = X0[k * PB + b];
                        const float* wp = W + k * 8;
                        acc[0] += xv * wp[0]; acc[1] += xv * wp[1];
                        acc[2] += xv * wp[2]; acc[3] += xv * wp[3];
                        acc[4] += xv * wp[4]; acc[5] += xv * wp[5];
                    }
                    wred(acc, 6);
                    if (lane < 6) {
                        float dot = acc[lane];
                        float mv;
                        if (t == 0) {
                            mv = fmaxf(dot, 0.f);
                        } else {
                            float mp = AUX[40 + b * 6 + lane];
                            mv = 0.2f * fmaxf(dot, 0.f) + 0.8f * mp + nse * mp * mp;
                        }
                        AUX[40 + b * 6 + lane] = mv;
                        g_mr[t & 7][b * 8 + lane] = mv;
                    }
                    __syncwarp();
                    if (lane < 2) {
                        int d = lane;
                        float pos, vel;
                        if (t == 0) {
                            pos = home[b * 2 + d];
                            vel = 0.f;
                        } else {
                            float tq = pse;
                            #pragma unroll
                            for (int j = 0; j < 6; j++)
                                tq += AUX[40 + b * 6 + j] * AUX[100 + j * 2 + d];
                            vel = AUX[b * 4 + 2 + d] + 0.01f * tq;
                            pos = AUX[b * 4 + d] + 0.01f * vel;
                        }
                        AUX[b * 4 + d]     = pos;
                        AUX[b * 4 + 2 + d] = vel;
                        out[t * 36 + b * 4 + d]     = pos;
                        out[t * 36 + b * 4 + 2 + d] = vel;
                    }
                }
            }
        }
        gridbar(tgt); tgt += GRIDN;
    }
}

extern "C" void kernel_launch(void* const* d_in, const int* in_sizes, int n_in,
                              void* d_out, int out_size) {
    // 0 des_targ (dead: scaled by 0), 1 perturb_seq, 2 noise_h1, 3 noise_h2,
    // 4 noise_m, 5 home, 6 W_in, 7 b_in, 8 W_in_self, 9 W_out, 10 b_out,
    // 11 W_out_self, 12 W_mus, 13 M_arm
    const float* pert = (const float*)d_in[1];
    const float* n1g  = (const float*)d_in[2];
    const float* n2g  = (const float*)d_in[3];
    const float* nmg  = (const float*)d_in[4];
    const float* home = (const float*)d_in[5];
    const float* Win  = (const float*)d_in[6];
    const float* bin  = (const float*)d_in[7];
    const float* Wsf1 = (const float*)d_in[8];
    const float* Wout = (const float*)d_in[9];
    const float* bout = (const float*)d_in[10];
    const float* Wsf2 = (const float*)d_in[11];
    const float* Wmus = (const float*)d_in[12];
    const float* Marm = (const float*)d_in[13];
    float* out = (float*)d_out;

    void *p;
    cudaGetSymbolAddress(&p, g_h1);  cudaMemsetAsync(p, 0, sizeof(g_h1),  0);
    cudaGetSymbolAddress(&p, g_h2);  cudaMemsetAsync(p, 0, sizeof(g_h2),  0);
    cudaGetSymbolAddress(&p, g_mr);  cudaMemsetAsync(p, 0, sizeof(g_mr),  0);
    cudaGetSymbolAddress(&p, g_bar); cudaMemsetAsync(p, 0, sizeof(g_bar), 0);

    cudaFuncSetAttribute(ctrl_kernel,
                         cudaFuncAttributeMaxDynamicSharedMemorySize, SMEMB);

    ctrl_kernel<<<GRIDN, NTHR, SMEMB, 0>>>(pert, n1g, n2g, nmg, home,
                                           Win, bin, Wsf1, Wout, bout,
                                           Wsf2, Wmus, Marm, out);
}

// round 5
// speedup vs baseline: 1.0014x; 1.0014x over previous
#include <cuda_runtime.h>
#include <math.h>

#define TT     4096
#define BB     9
#define KP     512
#define NA     48
#define NB     96
#define GRIDN  (NA + NB + 1)
#define NTHR   384
#define PB     12
#define SMEMB  ((6144 * 3 + 512) * 4)

// depth-8 generation rings
__device__ float    g_h1[8][KP * PB];
__device__ float    g_h2[8][KP * PB];
__device__ float    g_mr[8][BB * 8];
__device__ unsigned g_cnt[96];   // c_h1 = [0], c_h2 = [32], c_m = [64]

__device__ __forceinline__ unsigned ldacq(const unsigned* p) {
    unsigned v;
    asm volatile("ld.acquire.gpu.global.u32 %0, [%1];" : "=r"(v) : "l"(p));
    return v;
}
__device__ __forceinline__ void waitge(const unsigned* p, unsigned tgt) {
    while (ldacq(p) < tgt) { }
}
__device__ __forceinline__ void arrive(unsigned* p) {
    __syncthreads();
    if (threadIdx.x == 0) {
        __threadfence();
        asm volatile("red.release.gpu.global.add.u32 [%0], 1;" :: "l"(p));
    }
}

__device__ __forceinline__ void stage6144(float* dst, const float* src) {
    const float4* s = (const float4*)src;
    float4*       d = (float4*)dst;
    for (int i = threadIdx.x; i < (KP * PB) / 4; i += NTHR) d[i] = __ldcg(s + i);
}

__device__ __forceinline__ void wred(float* a, int n) {
    for (int o = 16; o; o >>= 1)
        for (int j = 0; j < n; j++) a[j] += __shfl_xor_sync(0xffffffffu, a[j], o);
}

__device__ __forceinline__ void rowdot9(const float* wrow, const float* x,
                                        float* acc, int lane) {
    #pragma unroll 4
    for (int k = lane; k < KP; k += 32) {
        float w = wrow[k];
        const float* xp = x + k * PB;
        float4 a = *(const float4*)(xp);
        float4 b = *(const float4*)(xp + 4);
        float  c = xp[8];
        acc[0] += w * a.x; acc[1] += w * a.y; acc[2] += w * a.z; acc[3] += w * a.w;
        acc[4] += w * b.x; acc[5] += w * b.y; acc[6] += w * b.z; acc[7] += w * b.w;
        acc[8] += w * c;
    }
}

// AUX offsets.
// role A: Win 0..131, home 140..157, bin 160..170, net_in 176..287
// role B: bout 0..15, partials 16..124
// role C: js 0..35, m_prev 40..95, M_arm 100..111, home 120..137

__global__ void __launch_bounds__(NTHR, 1)
ctrl_kernel(const float* __restrict__ pert,
            const float* __restrict__ n1g,  const float* __restrict__ n2g,
            const float* __restrict__ nmg,  const float* __restrict__ home,
            const float* __restrict__ Win,  const float* __restrict__ bin,
            const float* __restrict__ Wsf1, const float* __restrict__ Wout,
            const float* __restrict__ bout, const float* __restrict__ Wsf2,
            const float* __restrict__ Wmus, const float* __restrict__ Marm,
            float* __restrict__ out)
{
    extern __shared__ float sm[];
    float* X0  = sm;
    float* X1  = sm + 6144;
    float* W   = sm + 12288;
    float* AUX = sm + 18432;

    const int tid  = threadIdx.x;
    const int lane = tid & 31;
    const int wrp  = tid >> 5;
    const int bid  = blockIdx.x;
    const int role = (bid < NA) ? 0 : (bid < NA + NB ? 1 : 2);

    unsigned* c_h1 = &g_cnt[0];
    unsigned* c_h2 = &g_cnt[32];
    unsigned* c_m  = &g_cnt[64];

    if (role == 0) {
        // ------------------------------ stage A: h1 -------------------------
        const int r0 = (bid * 500) / NA;
        const int R  = ((bid + 1) * 500) / NA - r0;
        for (int i = tid; i < R * KP; i += NTHR) {
            int w = i / KP, k = i % KP;
            W[i] = (k < 500) ? Wsf1[(r0 + w) * 500 + k] : 0.f;
        }
        for (int i = tid; i < R * 12; i += NTHR)
            AUX[i] = Win[(r0 + i / 12) * 12 + (i % 12)];
        if (tid < R) AUX[160 + tid] = bin[r0 + tid];
        if (tid < 18) AUX[140 + tid] = home[tid];   // home cached (no overlap!)
        __syncthreads();

        // gen 0: h1(0) = tanh(b_in)
        if (wrp < R && lane < 9)
            g_h1[0][(r0 + wrp) * PB + lane] = tanhf(AUX[160 + wrp]);
        arrive(c_h1);

        for (int t = 1; t < TT; ++t) {
            float nse = 0.f;
            if (wrp < R && lane < 9)
                nse = n1g[(long)(t - 1) * (BB * 500) + lane * 500 + (r0 + wrp)];

            if (tid == 0) {
                int tm = t - 6; if (tm < 0) tm = 0;
                waitge(c_m,  (unsigned)(tm + 1));       // feedback gen tm done
                waitge(c_h1, 48u * (unsigned)t);        // h1(t-1) complete
                if (t >= 8) waitge(c_h2, 96u * (unsigned)(t - 7)); // slot reuse
            }
            __syncthreads();

            stage6144(X0, g_h1[(t - 1) & 7]);
            if (tid < 108) {
                int b = tid / 12, c = tid % 12;
                int t6 = t - 6; if (t6 < 0) t6 = 0;
                float v = 0.f;
                if (c >= 2 && c < 6) {
                    float js = __ldcg(out + t6 * 36 + b * 4 + (c - 2));
                    v = (c < 4) ? 2.0f * (js - AUX[140 + b * 2 + (c - 2)])
                                : 0.5f * js;
                } else if (c >= 6) {
                    v = __ldcg(&g_mr[t6 & 7][b * 8 + (c - 6)]);
                }
                AUX[176 + b * 12 + c] = v;
            }
            __syncthreads();

            if (wrp < R) {
                float acc[9] = {0,0,0,0,0,0,0,0,0};
                rowdot9(W + wrp * KP, X0, acc, lane);
                wred(acc, 9);
                if (lane < 9) {
                    int i = r0 + wrp, b = lane;
                    float pre = acc[b] + AUX[160 + wrp];
                    #pragma unroll
                    for (int c = 0; c < 12; c++)
                        pre += AUX[wrp * 12 + c] * AUX[176 + b * 12 + c];
                    float hp = X0[i * PB + b];
                    g_h1[t & 7][i * PB + b] =
                        0.5f * tanhf(pre) + 0.5f * hp + nse * hp * hp;
                }
            }
            arrive(c_h1);
        }
    } else if (role == 1) {
        // ------------------------------ stage B: h2 -------------------------
        const int b2 = bid - NA;
        const int r0 = (b2 * 500) / NB;
        const int R  = ((b2 + 1) * 500) / NB - r0;
        for (int i = tid; i < 2 * R * KP; i += NTHR) {
            int w = i / KP, k = i % KP;
            float v = 0.f;
            if (k < 500)
                v = (w < R) ? Wout[(r0 + w) * 500 + k]
                            : Wsf2[(r0 + w - R) * 500 + k];
            W[i] = v;
        }
        if (tid < R) AUX[tid] = bout[r0 + tid];
        __syncthreads();

        for (int t = 0; t < TT; ++t) {
            float nse = 0.f;
            if (t >= 1 && tid < R * 9)
                nse = n2g[(long)(t - 1) * (BB * 500)
                          + (tid % 9) * 500 + (r0 + tid / 9)];

            if (tid == 0) {
                waitge(c_h1, 48u * (unsigned)(t + 1));              // h1(t)
                if (t >= 1) waitge(c_h2, 96u * (unsigned)t);        // h2(t-1)
                if (t >= 8) waitge(c_m,  (unsigned)(t - 7));        // slot reuse
            }
            __syncthreads();

            stage6144(X0, g_h1[t & 7]);
            stage6144(X1, g_h2[(t - 1) & 7]);   // t=0: slot 7 is zeros
            __syncthreads();

            if (wrp < 2 * R) {
                float acc[9] = {0,0,0,0,0,0,0,0,0};
                rowdot9(W + wrp * KP, (wrp < R) ? X0 : X1, acc, lane);
                wred(acc, 9);
                if (lane < 9) AUX[16 + wrp * 9 + lane] = acc[lane];
            }
            __syncthreads();
            if (tid < R * 9) {
                int w = tid / 9, b = tid % 9, i = r0 + w;
                float pre = AUX[16 + w * 9 + b] + AUX[16 + (w + R) * 9 + b]
                          + AUX[w];
                float val;
                if (t == 0) {
                    val = tanhf(pre);
                } else {
                    float hp = X1[i * PB + b];
                    val = 0.5f * tanhf(pre) + 0.5f * hp + nse * hp * hp;
                }
                g_h2[t & 7][i * PB + b] = val;
            }
            arrive(c_h2);
        }
    } else {
        // ------------------------------ stage C: muscles + arm --------------
        for (int i = tid; i < KP * 8; i += NTHR) {
            int k = i / 8, j = i % 8;
            W[i] = (k < 500 && j < 6) ? Wmus[j * 500 + k] : 0.f;
        }
        if (tid < 12) AUX[100 + tid] = Marm[tid];
        if (tid < 18) AUX[120 + tid] = home[tid];
        __syncthreads();

        for (int t = 0; t < TT; ++t) {
            float nse = 0.f, pse = 0.f;
            if (t >= 1 && wrp < 9) {
                if (lane < 6)
                    nse = nmg[(long)(t - 1) * (BB * 6) + wrp * 6 + lane];
                if (lane < 2)
                    pse = pert[(long)(t - 1) * (BB * 2) + wrp * 2 + lane];
            }

            if (tid == 0) {
                waitge(c_h2, 96u * (unsigned)(t + 1));              // h2(t)
                if (t >= 8) waitge(c_h1, 48u * (unsigned)(t - 1));  // mr reuse
            }
            __syncthreads();

            stage6144(X0, g_h2[t & 7]);
            __syncthreads();

            if (wrp < 9) {
                int b = wrp;
                float acc[6] = {0,0,0,0,0,0};
                #pragma unroll 4
                for (int k = lane; k < KP; k += 32) {
                    float xv = X0[k * PB + b];
                    const float* wp = W + k * 8;
                    acc[0] += xv * wp[0]; acc[1] += xv * wp[1];
                    acc[2] += xv * wp[2]; acc[3] += xv * wp[3];
                    acc[4] += xv * wp[4]; acc[5] += xv * wp[5];
                }
                wred(acc, 6);
                if (lane < 6) {
                    float dot = acc[lane];
                    float mv;
                    if (t == 0) {
                        mv = fmaxf(dot, 0.f);
                    } else {
                        float mp = AUX[40 + b * 6 + lane];
                        mv = 0.2f * fmaxf(dot, 0.f) + 0.8f * mp + nse * mp * mp;
                    }
                    AUX[40 + b * 6 + lane] = mv;
                    g_mr[t & 7][b * 8 + lane] = mv;
                }
                __syncwarp();
                if (lane < 2) {
                    int d = lane;
                    float pos, vel;
                    if (t == 0) {
                        pos = AUX[120 + b * 2 + d];
                        vel = 0.f;
                    } else {
                        float tq = pse;
                        #pragma unroll
                        for (int j = 0; j < 6; j++)
                            tq += AUX[40 + b * 6 + j] * AUX[100 + j * 2 + d];
                        vel = AUX[b * 4 + 2 + d] + 0.01f * tq;
                        pos = AUX[b * 4 + d] + 0.01f * vel;
                    }
                    AUX[b * 4 + d]     = pos;
                    AUX[b * 4 + 2 + d] = vel;
                    out[t * 36 + b * 4 + d]     = pos;
                    out[t * 36 + b * 4 + 2 + d] = vel;
                }
            }
            arrive(c_m);
        }
    }
}

extern "C" void kernel_launch(void* const* d_in, const int* in_sizes, int n_in,
                              void* d_out, int out_size) {
    // 0 des_targ (dead: scaled by 0), 1 perturb_seq, 2 noise_h1, 3 noise_h2,
    // 4 noise_m, 5 home, 6 W_in, 7 b_in, 8 W_in_self, 9 W_out, 10 b_out,
    // 11 W_out_self, 12 W_mus, 13 M_arm
    const float* pert = (const float*)d_in[1];
    const float* n1g  = (const float*)d_in[2];
    const float* n2g  = (const float*)d_in[3];
    const float* nmg  = (const float*)d_in[4];
    const float* home = (const float*)d_in[5];
    const float* Win  = (const float*)d_in[6];
    const float* bin  = (const float*)d_in[7];
    const float* Wsf1 = (const float*)d_in[8];
    const float* Wout = (const float*)d_in[9];
    const float* bout = (const float*)d_in[10];
    const float* Wsf2 = (const float*)d_in[11];
    const float* Wmus = (const float*)d_in[12];
    const float* Marm = (const float*)d_in[13];
    float* out = (float*)d_out;

    void *p;
    cudaGetSymbolAddress(&p, g_h1);  cudaMemsetAsync(p, 0, sizeof(g_h1),  0);
    cudaGetSymbolAddress(&p, g_h2);  cudaMemsetAsync(p, 0, sizeof(g_h2),  0);
    cudaGetSymbolAddress(&p, g_mr);  cudaMemsetAsync(p, 0, sizeof(g_mr),  0);
    cudaGetSymbolAddress(&p, g_cnt); cudaMemsetAsync(p, 0, sizeof(g_cnt), 0);

    cudaFuncSetAttribute(ctrl_kernel,
                         cudaFuncAttributeMaxDynamicSharedMemorySize, SMEMB);

    ctrl_kernel<<<GRIDN, NTHR, SMEMB, 0>>>(pert, n1g, n2g, nmg, home,
                                           Win, bin, Wsf1, Wout, bout,
                                           Wsf2, Wmus, Marm, out);
}

// round 6
// speedup vs baseline: 1.1972x; 1.1955x over previous
#include <cuda_runtime.h>
#include <math.h>

#define TT     4096
#define NA     48
#define NB     96
#define GRIDN  (NA + NB + 1)
#define NTHR   384
#define VEC    4608              // 9 * 512, transposed state [b][512]
#define SMEMB  ((4608*2 + 6144 + 512) * 4)

// depth-8 generation rings (transposed: [b*512 + row])
__device__ float    g_h1t[8][VEC];
__device__ float    g_h2t[8][VEC];
__device__ float    g_mr[8][72];      // [b*8 + mus]
__device__ unsigned g_cnt[96];        // c_h1=[0], c_h2=[32], c_m=[64]

__device__ __forceinline__ unsigned ldacq(const unsigned* p) {
    unsigned v;
    asm volatile("ld.acquire.gpu.global.u32 %0, [%1];" : "=r"(v) : "l"(p));
    return v;
}
__device__ __forceinline__ void waitge(const unsigned* p, unsigned tgt) {
    while (ldacq(p) < tgt) { }
}
__device__ __forceinline__ void arrive(unsigned* p) {
    __syncthreads();
    if (threadIdx.x == 0) {
        __threadfence();
        asm volatile("red.release.gpu.global.add.u32 [%0], 1;" :: "l"(p));
    }
}

// copy one transposed state vector (4608 floats) L2 -> SMEM, conflict-free
__device__ __forceinline__ void stageT(float* dst, const float* src) {
    const float4* s = (const float4*)src;
    float4*       d = (float4*)dst;
    for (int i = threadIdx.x; i < VEC / 4; i += NTHR) d[i] = __ldcg(s + i);
}

// 3-row x 9-batch register-blocked GEMV over k=0..511.
// Xb[b*512+k] conflict-free; Wb = 3 rows, 512 pitch. Result: a[j*9+b] summed
// across all 32 lanes (butterfly).
__device__ __forceinline__ void gemv3(const float* __restrict__ Xb,
                                      const float* __restrict__ Wb,
                                      float* a, int lane) {
    #pragma unroll
    for (int q = 0; q < 27; q++) a[q] = 0.f;
    #pragma unroll 4
    for (int it = 0; it < 16; ++it) {
        int k = lane + 32 * it;
        float xv[9];
        #pragma unroll
        for (int b = 0; b < 9; b++) xv[b] = Xb[b * 512 + k];
        #pragma unroll
        for (int j = 0; j < 3; j++) {
            float w = Wb[j * 512 + k];
            #pragma unroll
            for (int b = 0; b < 9; b++) a[j * 9 + b] = fmaf(w, xv[b], a[j * 9 + b]);
        }
    }
    #pragma unroll
    for (int o = 16; o; o >>= 1)
        #pragma unroll
        for (int q = 0; q < 27; q++)
            a[q] += __shfl_xor_sync(0xffffffffu, a[q], o);
}
__device__ __forceinline__ float sel27(const float* a, int lane) {
    float v = 0.f;
    #pragma unroll
    for (int q = 0; q < 27; q++) if (lane == q) v = a[q];
    return v;
}

// AUX layouts:
// A: Win 0..143, home 144..161, bin 176..187, net_in 200..307
// B: bout 0..5, partials 64..127
// C: js 0..35, m_prev 40..93, M_arm 100..111, home 120..137

__global__ void __launch_bounds__(NTHR, 1)
ctrl_kernel(const float* __restrict__ pert,
            const float* __restrict__ n1g,  const float* __restrict__ n2g,
            const float* __restrict__ nmg,  const float* __restrict__ home,
            const float* __restrict__ Win,  const float* __restrict__ bin,
            const float* __restrict__ Wsf1, const float* __restrict__ Wout,
            const float* __restrict__ bout, const float* __restrict__ Wsf2,
            const float* __restrict__ Wmus, const float* __restrict__ Marm,
            float* __restrict__ out)
{
    extern __shared__ float sm[];
    float* X0  = sm;             // 4608
    float* X1  = sm + 4608;      // 4608
    float* W   = sm + 9216;      // 12 rows x 512 = 6144
    float* AUX = sm + 15360;     // 512

    const int tid  = threadIdx.x;
    const int lane = tid & 31;
    const int wrp  = tid >> 5;
    const int bid  = blockIdx.x;
    const int role = (bid < NA) ? 0 : (bid < NA + NB ? 1 : 2);

    unsigned* c_h1 = &g_cnt[0];
    unsigned* c_h2 = &g_cnt[32];
    unsigned* c_m  = &g_cnt[64];

    // per-lane GEMV coordinates (used guarded)
    const int vr = wrp * 3 + lane / 9;   // virtual row within CTA (warp<4)
    const int b9 = lane % 9;

    if (role == 0) {
        // ============================ stage A: h1 ===========================
        const int r0 = (bid * 500) / NA;
        const int R  = ((bid + 1) * 500) / NA - r0;
        for (int i = tid; i < 12 * 512; i += NTHR) {
            int w = i >> 9, k = i & 511;
            W[i] = (w < R && k < 500) ? Wsf1[(r0 + w) * 500 + k] : 0.f;
        }
        for (int i = tid; i < R * 12; i += NTHR)
            AUX[i] = Win[(r0 + i / 12) * 12 + (i % 12)];
        if (tid < 18) AUX[144 + tid] = home[tid];
        if (tid < R)  AUX[176 + tid] = bin[r0 + tid];
        __syncthreads();

        // gen 0: h1(0) = tanh(b_in) for this CTA's rows, all batches
        if (tid < 99) {
            int w = tid / 9, bb = tid % 9;
            if (w < R)
                g_h1t[0][bb * 512 + (r0 + w)] = tanhf(AUX[176 + w]);
        }
        arrive(c_h1);

        for (int t = 1; t < TT; ++t) {
            const bool ok = (wrp < 4) && (lane < 27) && (vr < R);
            const int  gi = r0 + vr;
            float nse = 0.f;
            if (ok)
                nse = n1g[(size_t)(t - 1) * 4500 + b9 * 500 + gi];

            if (tid == 0) {
                int tm = t - 6; if (tm < 0) tm = 0;
                waitge(c_m,  (unsigned)(tm + 1));
                waitge(c_h1, 48u * (unsigned)t);
                if (t >= 8) waitge(c_h2, 96u * (unsigned)(t - 7));
            }
            __syncthreads();

            stageT(X0, g_h1t[(t - 1) & 7]);
            if (tid < 108) {
                int bb = tid / 12, c = tid % 12;
                int t6 = t - 6; if (t6 < 0) t6 = 0;
                float v = 0.f;
                if (c >= 2 && c < 6) {
                    float js = __ldcg(out + t6 * 36 + bb * 4 + (c - 2));
                    v = (c < 4) ? 2.0f * (js - AUX[144 + bb * 2 + (c - 2)])
                                : 0.5f * js;
                } else if (c >= 6) {
                    v = __ldcg(&g_mr[t6 & 7][bb * 8 + (c - 6)]);
                }
                AUX[200 + bb * 12 + c] = v;
            }
            __syncthreads();

            if (wrp < 4) {
                float a[27];
                gemv3(X0, W + wrp * 3 * 512, a, lane);
                float v = sel27(a, lane);
                if (ok) {
                    float pre = v + AUX[176 + vr];
                    #pragma unroll
                    for (int c = 0; c < 12; c++)
                        pre += AUX[vr * 12 + c] * AUX[200 + b9 * 12 + c];
                    float hp = X0[b9 * 512 + gi];
                    g_h1t[t & 7][b9 * 512 + gi] =
                        0.5f * tanhf(pre) + 0.5f * hp + nse * hp * hp;
                }
            }
            arrive(c_h1);
        }
    } else if (role == 1) {
        // ============================ stage B: h2 ===========================
        const int b2 = bid - NA;
        const int r0 = (b2 * 500) / NB;
        const int R  = ((b2 + 1) * 500) / NB - r0;
        // W rows 0..5: Wout local rows; rows 6..11: Wsf2 local rows
        for (int i = tid; i < 12 * 512; i += NTHR) {
            int w = i >> 9, k = i & 511;
            float v = 0.f;
            if (k < 500) {
                if (w < 6) { if (w < R)     v = Wout[(r0 + w) * 500 + k]; }
                else       { if (w - 6 < R) v = Wsf2[(r0 + w - 6) * 500 + k]; }
            }
            W[i] = v;
        }
        if (tid < R) AUX[tid] = bout[r0 + tid];
        __syncthreads();

        for (int t = 0; t < TT; ++t) {
            const bool ok = (wrp < 2) && (lane < 27) && (vr < R);
            const int  gi = r0 + vr;
            float nse = 0.f;
            if (t >= 1 && ok)
                nse = n2g[(size_t)(t - 1) * 4500 + b9 * 500 + gi];

            if (tid == 0) {
                waitge(c_h1, 48u * (unsigned)(t + 1));
                if (t >= 1) waitge(c_h2, 96u * (unsigned)t);
                if (t >= 8) waitge(c_m,  (unsigned)(t - 7));
            }
            __syncthreads();

            stageT(X0, g_h1t[t & 7]);
            stageT(X1, g_h2t[(t - 1) & 7]);   // t=0: slot 7 is zeros
            __syncthreads();

            float v = 0.f;
            if (wrp < 4) {
                float a[27];
                gemv3((wrp < 2) ? X0 : X1, W + wrp * 3 * 512, a, lane);
                v = sel27(a, lane);
                if (wrp >= 2 && lane < 27)
                    AUX[64 + (wrp - 2) * 32 + lane] = v;   // Wsf2 partials
            }
            __syncthreads();
            if (ok) {
                float pre = v + AUX[64 + wrp * 32 + lane] + AUX[vr];
                float val;
                if (t == 0) {
                    val = tanhf(pre);
                } else {
                    float hp = X1[b9 * 512 + gi];
                    val = 0.5f * tanhf(pre) + 0.5f * hp + nse * hp * hp;
                }
                g_h2t[t & 7][b9 * 512 + gi] = val;
            }
            arrive(c_h2);
        }
    } else {
        // ====================== stage C: muscles + arm ======================
        for (int i = tid; i < 6 * 512; i += NTHR) {
            int w = i >> 9, k = i & 511;
            W[i] = (k < 500) ? Wmus[w * 500 + k] : 0.f;
        }
        if (tid < 12) AUX[100 + tid] = Marm[tid];
        if (tid < 18) AUX[120 + tid] = home[tid];
        __syncthreads();

        for (int t = 0; t < TT; ++t) {
            const bool ok  = (wrp < 2) && (lane < 27);   // mus = vr (0..5)
            float nse = 0.f, pse = 0.f;
            if (t >= 1) {
                if (ok)       nse = nmg[(size_t)(t - 1) * 54 + b9 * 6 + vr];
                if (tid < 18) pse = pert[(size_t)(t - 1) * 18 + tid];
            }

            if (tid == 0) {
                waitge(c_h2, 96u * (unsigned)(t + 1));
                if (t >= 8) waitge(c_h1, 48u * (unsigned)(t - 1));
            }
            __syncthreads();

            stageT(X0, g_h2t[t & 7]);
            __syncthreads();

            if (wrp < 2) {
                float a[27];
                gemv3(X0, W + wrp * 3 * 512, a, lane);
                float v = sel27(a, lane);
                if (lane < 27) {
                    float dot = fmaxf(v, 0.f);
                    float mv;
                    if (t == 0) {
                        mv = dot;
                    } else {
                        float mp = AUX[40 + b9 * 6 + vr];
                        mv = 0.2f * dot + 0.8f * mp + nse * mp * mp;
                    }
                    AUX[40 + b9 * 6 + vr] = mv;
                    g_mr[t & 7][b9 * 8 + vr] = mv;
                }
            }
            __syncthreads();
            if (tid < 18) {
                int bb = tid / 2, d = tid % 2;
                float pos, vel;
                if (t == 0) {
                    pos = AUX[120 + bb * 2 + d];
                    vel = 0.f;
                } else {
                    float tq = pse;
                    #pragma unroll
                    for (int j = 0; j < 6; j++)
                        tq += AUX[40 + bb * 6 + j] * AUX[100 + j * 2 + d];
                    vel = AUX[bb * 4 + 2 + d] + 0.01f * tq;
                    pos = AUX[bb * 4 + d] + 0.01f * vel;
                }
                AUX[bb * 4 + d]     = pos;
                AUX[bb * 4 + 2 + d] = vel;
                out[t * 36 + bb * 4 + d]     = pos;
                out[t * 36 + bb * 4 + 2 + d] = vel;
            }
            arrive(c_m);
        }
    }
}

extern "C" void kernel_launch(void* const* d_in, const int* in_sizes, int n_in,
                              void* d_out, int out_size) {
    // 0 des_targ (dead: scaled by 0), 1 perturb_seq, 2 noise_h1, 3 noise_h2,
    // 4 noise_m, 5 home, 6 W_in, 7 b_in, 8 W_in_self, 9 W_out, 10 b_out,
    // 11 W_out_self, 12 W_mus, 13 M_arm
    const float* pert = (const float*)d_in[1];
    const float* n1g  = (const float*)d_in[2];
    const float* n2g  = (const float*)d_in[3];
    const float* nmg  = (const float*)d_in[4];
    const float* home = (const float*)d_in[5];
    const float* Win  = (const float*)d_in[6];
    const float* bin  = (const float*)d_in[7];
    const float* Wsf1 = (const float*)d_in[8];
    const float* Wout = (const float*)d_in[9];
    const float* bout = (const float*)d_in[10];
    const float* Wsf2 = (const float*)d_in[11];
    const float* Wmus = (const float*)d_in[12];
    const float* Marm = (const float*)d_in[13];
    float* out = (float*)d_out;

    void *p;
    cudaGetSymbolAddress(&p, g_h1t); cudaMemsetAsync(p, 0, sizeof(g_h1t), 0);
    cudaGetSymbolAddress(&p, g_h2t); cudaMemsetAsync(p, 0, sizeof(g_h2t), 0);
    cudaGetSymbolAddress(&p, g_mr);  cudaMemsetAsync(p, 0, sizeof(g_mr),  0);
    cudaGetSymbolAddress(&p, g_cnt); cudaMemsetAsync(p, 0, sizeof(g_cnt), 0);

    cudaFuncSetAttribute(ctrl_kernel,
                         cudaFuncAttributeMaxDynamicSharedMemorySize, SMEMB);

    ctrl_kernel<<<GRIDN, NTHR, SMEMB, 0>>>(pert, n1g, n2g, nmg, home,
                                           Win, bin, Wsf1, Wout, bout,
                                           Wsf2, Wmus, Marm, out);
}

// round 7
// speedup vs baseline: 1.5707x; 1.3120x over previous
#include <cuda_runtime.h>
#include <math.h>

#define TT     4096
#define GRIDN  144            // 9 groups x 16 CTAs (A:5, B:10, C:1)
#define NTHR   384
#define SMEMB  214368         // floats: X0 512 | X1 512 | AUX 64 | bin 104 | Win 1200 | W 51200

// per-group depth-8 rings (batch-partitioned)
__device__ float    g_h1r[9][8][512];
__device__ float    g_h2r[9][8][512];
__device__ float    g_mrr[9][8][8];
__device__ unsigned g_cnt[9 * 96];    // per group: c_h1=+0, c_h2=+32, c_m=+64

__device__ __forceinline__ unsigned ldacq(const unsigned* p) {
    unsigned v;
    asm volatile("ld.acquire.gpu.global.u32 %0, [%1];" : "=r"(v) : "l"(p));
    return v;
}
__device__ __forceinline__ void waitge(const unsigned* p, unsigned tgt) {
    while (ldacq(p) < tgt) { }
}
__device__ __forceinline__ void arrive(unsigned* p) {
    __syncthreads();
    if (threadIdx.x == 0) {
        __threadfence();
        asm volatile("red.release.gpu.global.add.u32 [%0], 1;" :: "l"(p));
    }
}

template <int N>
__device__ __forceinline__ void bfly(float* a) {
    #pragma unroll
    for (int o = 16; o; o >>= 1)
        #pragma unroll
        for (int q = 0; q < N; q++) a[q] += __shfl_xor_sync(0xffffffffu, a[q], o);
}
template <int N>
__device__ __forceinline__ float sel(const float* a, int lane) {
    float v = 0.f;
    #pragma unroll
    for (int q = 0; q < N; q++) if (lane == q) v = a[q];
    return v;
}

__global__ void __launch_bounds__(NTHR, 1)
ctrl_kernel(const float* __restrict__ pert,
            const float* __restrict__ n1g,  const float* __restrict__ n2g,
            const float* __restrict__ nmg,  const float* __restrict__ home,
            const float* __restrict__ Win,  const float* __restrict__ bin,
            const float* __restrict__ Wsf1, const float* __restrict__ Wout,
            const float* __restrict__ bout, const float* __restrict__ Wsf2,
            const float* __restrict__ Wmus, const float* __restrict__ Marm,
            float* __restrict__ out)
{
    extern __shared__ float sm[];
    float* X0    = sm;            // 512: current input vector
    float* X1    = sm + 512;      // 512: second input (B only)
    float* AUX   = sm + 1024;     // 64
    float* bin_s = sm + 1088;     // 104: bias slice
    float* Win_s = sm + 1192;     // 1200: W_in rows (A only)
    float* W     = sm + 2392;     // 51200: weight rows, 512 pitch

    const int tid  = threadIdx.x;
    const int lane = tid & 31;
    const int wrp  = tid >> 5;
    const int bid  = blockIdx.x;
    const int gid  = bid >> 4;          // group = batch
    const int loc  = bid & 15;
    const int b    = gid;

    unsigned* c_h1 = &g_cnt[gid * 96];
    unsigned* c_h2 = c_h1 + 32;
    unsigned* c_m  = c_h1 + 64;

    const float4* Xv0 = (const float4*)X0;
    const float4* Xv1 = (const float4*)X1;
    const float4* Wv  = (const float4*)W;

    if (loc < 5) {
        // ============================ stage A: h1 ===========================
        const int r0 = loc * 100;
        for (int i = tid; i < 51200; i += NTHR) {
            int r = i >> 9, k = i & 511;
            W[i] = (k < 500) ? Wsf1[(r0 + r) * 500 + k] : 0.f;
        }
        for (int i = tid; i < 1200; i += NTHR)
            Win_s[i] = Win[(r0 + i / 12) * 12 + (i % 12)];
        for (int i = tid; i < 100; i += NTHR) bin_s[i] = bin[r0 + i];
        if (tid < 2) AUX[16 + tid] = home[b * 2 + tid];
        __syncthreads();

        // gen 0: h1(0) = tanh(b_in)
        for (int i = tid; i < 100; i += NTHR)
            g_h1r[gid][0][r0 + i] = tanhf(bin_s[i]);
        arrive(c_h1);

        const int rbase = wrp * 9;                         // warps 0..10: 9 rows, warp 11: 1
        const int nr    = (100 - rbase < 9) ? (100 - rbase) : 9;

        for (int t = 1; t < TT; ++t) {
            float nse = 0.f;
            if (lane < nr)
                nse = n1g[(size_t)(t - 1) * 4500 + b * 500 + (r0 + rbase + lane)];

            int tm = t - 6; if (tm < 0) tm = 0;
            waitge(c_m,  (unsigned)(tm + 1));               // feedback tm done
            waitge(c_h1, 5u * (unsigned)t);                 // h1(t-1) complete
            if (t >= 8) waitge(c_h2, 10u * (unsigned)(t - 7));  // ring WAR

            if (tid < 128) {
                ((float4*)X0)[tid] =
                    __ldcg((const float4*)g_h1r[gid][(t - 1) & 7] + tid);
            } else if (tid < 140) {
                int c = tid - 128;
                int t6 = t - 6; if (t6 < 0) t6 = 0;
                float v = 0.f;
                if (c >= 2 && c < 6) {
                    float js = __ldcg(out + t6 * 36 + b * 4 + (c - 2));
                    v = (c < 4) ? 2.0f * (js - AUX[16 + (c - 2)]) : 0.5f * js;
                } else if (c >= 6) {
                    v = __ldcg(&g_mrr[gid][t6 & 7][c - 6]);
                }
                AUX[c] = v;
            }
            __syncthreads();

            float acc[9];
            #pragma unroll
            for (int r = 0; r < 9; r++) acc[r] = 0.f;
            #pragma unroll
            for (int it = 0; it < 4; ++it) {
                int ch = lane + 32 * it;
                float4 x = Xv0[ch];
                #pragma unroll
                for (int r = 0; r < 9; r++) {
                    int rl = rbase + r; if (rl > 99) rl = 99;
                    float4 w = Wv[rl * 128 + ch];
                    acc[r] += w.x * x.x + w.y * x.y + w.z * x.z + w.w * x.w;
                }
            }
            bfly<9>(acc);
            float v = sel<9>(acc, lane);
            if (lane < nr) {
                int rl = rbase + lane, grow = r0 + rl;
                float pre = v + bin_s[rl];
                #pragma unroll
                for (int c = 0; c < 12; c++)
                    pre += Win_s[rl * 12 + c] * AUX[c];
                float hp = X0[grow];
                g_h1r[gid][t & 7][grow] =
                    0.5f * tanhf(pre) + 0.5f * hp + nse * hp * hp;
            }
            arrive(c_h1);
        }
    } else if (loc < 15) {
        // ============================ stage B: h2 ===========================
        const int r0 = (loc - 5) * 50;
        for (int i = tid; i < 51200; i += NTHR) {
            int r = i >> 9, k = i & 511;
            float v = 0.f;
            if (k < 500)
                v = (r < 50) ? Wout[(r0 + r) * 500 + k]
                             : Wsf2[(r0 + r - 50) * 500 + k];
            W[i] = v;
        }
        for (int i = tid; i < 50; i += NTHR) bin_s[i] = bout[r0 + i];
        __syncthreads();

        const int rbase = (wrp < 2) ? wrp * 5 : 10 + (wrp - 2) * 4;
        const int nr    = (wrp < 2) ? 5 : 4;

        for (int t = 0; t < TT; ++t) {
            float nse = 0.f;
            if (t >= 1 && lane < nr)
                nse = n2g[(size_t)(t - 1) * 4500 + b * 500 + (r0 + rbase + lane)];

            waitge(c_h1, 5u * (unsigned)(t + 1));            // h1(t)
            if (t >= 1) waitge(c_h2, 10u * (unsigned)t);     // h2(t-1)
            if (t >= 8) waitge(c_m,  (unsigned)(t - 7));     // ring WAR

            if (tid < 128)
                ((float4*)X0)[tid] =
                    __ldcg((const float4*)g_h1r[gid][t & 7] + tid);
            else if (tid < 256)
                ((float4*)X1)[tid - 128] =
                    __ldcg((const float4*)g_h2r[gid][(t - 1) & 7] + (tid - 128));
            __syncthreads();

            float acc[5];
            #pragma unroll
            for (int r = 0; r < 5; r++) acc[r] = 0.f;
            #pragma unroll
            for (int it = 0; it < 4; ++it) {
                int ch = lane + 32 * it;
                float4 x0 = Xv0[ch];
                float4 x1 = Xv1[ch];
                #pragma unroll
                for (int r = 0; r < 5; r++) {
                    int rl = rbase + r; if (rl > 49) rl = 49;
                    float4 wo = Wv[rl * 128 + ch];
                    float4 ws = Wv[(50 + rl) * 128 + ch];
                    acc[r] += wo.x * x0.x + wo.y * x0.y + wo.z * x0.z + wo.w * x0.w
                            + ws.x * x1.x + ws.y * x1.y + ws.z * x1.z + ws.w * x1.w;
                }
            }
            bfly<5>(acc);
            float v = sel<5>(acc, lane);
            if (lane < nr) {
                int rl = rbase + lane, grow = r0 + rl;
                float pre = v + bin_s[rl];
                float val;
                if (t == 0) {
                    val = tanhf(pre);
                } else {
                    float hp = X1[grow];
                    val = 0.5f * tanhf(pre) + 0.5f * hp + nse * hp * hp;
                }
                g_h2r[gid][t & 7][grow] = val;
            }
            arrive(c_h2);
        }
    } else {
        // ====================== stage C: muscles + arm ======================
        for (int i = tid; i < 6 * 512; i += NTHR) {
            int r = i >> 9, k = i & 511;
            W[i] = (k < 500) ? Wmus[r * 500 + k] : 0.f;
        }
        if (tid < 12) AUX[32 + tid] = Marm[tid];
        if (tid < 2)  AUX[48 + tid] = home[b * 2 + tid];
        __syncthreads();

        for (int t = 0; t < TT; ++t) {
            float nse = 0.f, pse = 0.f;
            if (t >= 1 && wrp == 0) {
                if (lane < 6) nse = nmg[(size_t)(t - 1) * 54 + b * 6 + lane];
                if (lane < 2) pse = pert[(size_t)(t - 1) * 18 + b * 2 + lane];
            }

            waitge(c_h2, 10u * (unsigned)(t + 1));           // h2(t)
            if (t >= 8) waitge(c_h1, 5u * (unsigned)(t - 1)); // mr ring WAR

            if (tid < 128)
                ((float4*)X0)[tid] =
                    __ldcg((const float4*)g_h2r[gid][t & 7] + tid);
            __syncthreads();

            if (wrp == 0) {
                float acc[6];
                #pragma unroll
                for (int r = 0; r < 6; r++) acc[r] = 0.f;
                #pragma unroll
                for (int it = 0; it < 4; ++it) {
                    int ch = lane + 32 * it;
                    float4 x = Xv0[ch];
                    #pragma unroll
                    for (int r = 0; r < 6; r++) {
                        float4 w = Wv[r * 128 + ch];
                        acc[r] += w.x * x.x + w.y * x.y + w.z * x.z + w.w * x.w;
                    }
                }
                bfly<6>(acc);
                float v = sel<6>(acc, lane);
                if (lane < 6) {
                    float dot = fmaxf(v, 0.f);
                    float mv;
                    if (t == 0) {
                        mv = dot;
                    } else {
                        float mp = AUX[8 + lane];
                        mv = 0.2f * dot + 0.8f * mp + nse * mp * mp;
                    }
                    AUX[8 + lane] = mv;
                    g_mrr[gid][t & 7][lane] = mv;
                }
                __syncwarp();
                if (lane < 2) {
                    int d = lane;
                    float pos, vel;
                    if (t == 0) {
                        pos = AUX[48 + d];
                        vel = 0.f;
                    } else {
                        float tq = pse;
                        #pragma unroll
                        for (int j = 0; j < 6; j++)
                            tq += AUX[8 + j] * AUX[32 + j * 2 + d];
                        vel = AUX[2 + d] + 0.01f * tq;
                        pos = AUX[0 + d] + 0.01f * vel;
                    }
                    AUX[0 + d] = pos;
                    AUX[2 + d] = vel;
                    out[t * 36 + b * 4 + d]     = pos;
                    out[t * 36 + b * 4 + 2 + d] = vel;
                }
            }
            arrive(c_m);
        }
    }
}

extern "C" void kernel_launch(void* const* d_in, const int* in_sizes, int n_in,
                              void* d_out, int out_size) {
    // 0 des_targ (dead: scaled by 0), 1 perturb_seq, 2 noise_h1, 3 noise_h2,
    // 4 noise_m, 5 home, 6 W_in, 7 b_in, 8 W_in_self, 9 W_out, 10 b_out,
    // 11 W_out_self, 12 W_mus, 13 M_arm
    const float* pert = (const float*)d_in[1];
    const float* n1g  = (const float*)d_in[2];
    const float* n2g  = (const float*)d_in[3];
    const float* nmg  = (const float*)d_in[4];
    const float* home = (const float*)d_in[5];
    const float* Win  = (const float*)d_in[6];
    const float* bin  = (const float*)d_in[7];
    const float* Wsf1 = (const float*)d_in[8];
    const float* Wout = (const float*)d_in[9];
    const float* bout = (const float*)d_in[10];
    const float* Wsf2 = (const float*)d_in[11];
    const float* Wmus = (const float*)d_in[12];
    const float* Marm = (const float*)d_in[13];
    float* out = (float*)d_out;

    void *p;
    cudaGetSymbolAddress(&p, g_h1r); cudaMemsetAsync(p, 0, sizeof(g_h1r), 0);
    cudaGetSymbolAddress(&p, g_h2r); cudaMemsetAsync(p, 0, sizeof(g_h2r), 0);
    cudaGetSymbolAddress(&p, g_mrr); cudaMemsetAsync(p, 0, sizeof(g_mrr), 0);
    cudaGetSymbolAddress(&p, g_cnt); cudaMemsetAsync(p, 0, sizeof(g_cnt), 0);

    cudaFuncSetAttribute(ctrl_kernel,
                         cudaFuncAttributeMaxDynamicSharedMemorySize, SMEMB);

    ctrl_kernel<<<GRIDN, NTHR, SMEMB, 0>>>(pert, n1g, n2g, nmg, home,
                                           Win, bin, Wsf1, Wout, bout,
                                           Wsf2, Wmus, Marm, out);
}

// round 8
// speedup vs baseline: 1.7235x; 1.0973x over previous
#include <cuda_runtime.h>
#include <math.h>

#define TT     4096
#define NTHR   384
#define GRIDN  144            // 9 batches x (A:5, B1:5, B2:5, C:1)
#define SMEMB  212416

// depth-8 L2 rings, batch-partitioned
__device__ float    g_h1[9][8][512];
__device__ float    g_h2[9][8][512];
__device__ float    g_p1[9][8][512];   // B1 partials (Wout @ h1), by global row
__device__ float    g_fb[9][8][16];    // m[0..5], pos[6..7], vel[8..9]
__device__ unsigned g_cnt[9 * 128];    // per batch: c_h1@0 c_h2@8 c_m@16 c_p1[i]@24+8i

__device__ __forceinline__ unsigned ldacq(const unsigned* p) {
    unsigned v;
    asm volatile("ld.acquire.gpu.global.u32 %0, [%1];" : "=r"(v) : "l"(p));
    return v;
}
__device__ __forceinline__ void redrel(unsigned* p) {
    asm volatile("red.release.gpu.global.add.u32 [%0], 1;" :: "l"(p));
}

template <int N>
__device__ __forceinline__ void bfly(float* a) {
    #pragma unroll
    for (int o = 16; o; o >>= 1)
        #pragma unroll
        for (int q = 0; q < N; q++) a[q] += __shfl_xor_sync(0xffffffffu, a[q], o);
}
template <int N>
__device__ __forceinline__ float sel(const float* a, int lane) {
    float v = 0.f;
    #pragma unroll
    for (int q = 0; q < N; q++) if (lane == q) v = a[q];
    return v;
}

// 100-row GEMV: warp wrp handles rows rbase..rbase+nr-1 (8 or 9), full lanes over k
__device__ __forceinline__ float gemv100(const float4* Xv, const float4* Wv,
                                         int rbase, int lane) {
    float acc[9];
    #pragma unroll
    for (int r = 0; r < 9; r++) acc[r] = 0.f;
    #pragma unroll
    for (int it = 0; it < 4; ++it) {
        int ch = lane + 32 * it;
        float4 x = Xv[ch];
        #pragma unroll
        for (int r = 0; r < 9; r++) {
            int rl = rbase + r; if (rl > 99) rl = 99;
            float4 w = Wv[rl * 128 + ch];
            acc[r] += w.x * x.x + w.y * x.y + w.z * x.z + w.w * x.w;
        }
    }
    bfly<9>(acc);
    return sel<9>(acc, lane);
}

__global__ void __launch_bounds__(NTHR, 1)
ctrl_kernel(const float* __restrict__ pert,
            const float* __restrict__ n1g,  const float* __restrict__ n2g,
            const float* __restrict__ nmg,  const float* __restrict__ home,
            const float* __restrict__ Win,  const float* __restrict__ bin,
            const float* __restrict__ Wsf1, const float* __restrict__ Wout,
            const float* __restrict__ bout, const float* __restrict__ Wsf2,
            const float* __restrict__ Wmus, const float* __restrict__ Marm,
            float* __restrict__ out)
{
    extern __shared__ float sm[];
    float* X0    = sm;            // 512
    float* AUX   = sm + 512;      // 64
    float* bias  = sm + 576;      // 128
    float* Win_s = sm + 704;      // 1200 (A only)
    float* W     = sm + 1904;     // 51200

    const int tid  = threadIdx.x;
    const int lane = tid & 31;
    const int wrp  = tid >> 5;
    const int bid  = blockIdx.x;
    const int g    = bid >> 4;
    const int loc  = bid & 15;
    const int b    = g;

    unsigned* cb   = &g_cnt[g * 128];
    unsigned* c_h1 = cb;
    unsigned* c_h2 = cb + 8;
    unsigned* c_m  = cb + 16;

    const float4* Xv = (const float4*)X0;
    const float4* Wv = (const float4*)W;
    const int rbase = (wrp * 100) / 12;
    const int nr    = ((wrp + 1) * 100) / 12 - rbase;

    if (loc < 5) {
        // ============================ A: h1 =================================
        const int r0 = loc * 100;
        for (int i = tid; i < 51200; i += NTHR) {
            int r = i >> 9, k = i & 511;
            W[i] = (k < 500) ? Wsf1[(r0 + r) * 500 + k] : 0.f;
        }
        for (int i = tid; i < 1200; i += NTHR)
            Win_s[i] = Win[(r0 + i / 12) * 12 + (i % 12)];
        for (int i = tid; i < 100; i += NTHR) bias[i] = bin[r0 + i];
        if (tid < 2) AUX[32 + tid] = home[b * 2 + tid];
        __syncthreads();

        if (tid < 100) g_h1[g][0][r0 + tid] = tanhf(bias[tid]);   // h1(0)
        __syncthreads();
        if (tid == 0) redrel(c_h1);

        for (int t = 1; t < TT; ++t) {
            float nse = 0.f;
            if (lane < nr)
                nse = n1g[(size_t)(t - 1) * 4500 + b * 500 + (r0 + rbase + lane)];

            if (tid == 0) {
                int tm = t - 6; if (tm < 0) tm = 0;
                unsigned w1 = 5u * (unsigned)t, w2 = (unsigned)(tm + 1);
                for (;;) {
                    unsigned a = ldacq(c_h1);
                    unsigned c = ldacq(c_m);
                    if (a >= w1 && c >= w2) break;
                }
            }
            __syncthreads();

            if (tid < 128) {
                ((float4*)X0)[tid] =
                    __ldcg((const float4*)g_h1[g][(t - 1) & 7] + tid);
            } else if (tid < 140) {
                int c = tid - 128;
                int t6 = t - 6; if (t6 < 0) t6 = 0;
                const float* fb = g_fb[g][t6 & 7];
                float v = 0.f;
                if (c >= 2 && c < 4)      v = 2.0f * (__ldcg(fb + 6 + (c - 2)) - AUX[32 + (c - 2)]);
                else if (c >= 4 && c < 6) v = 0.5f * __ldcg(fb + 8 + (c - 4));
                else if (c >= 6)          v = __ldcg(fb + (c - 6));
                AUX[c] = v;
            }
            __syncthreads();

            float v = gemv100(Xv, Wv, rbase, lane);
            if (lane < nr) {
                int rl = rbase + lane, grow = r0 + rl;
                float pre = v + bias[rl];
                #pragma unroll
                for (int c = 0; c < 12; c++)
                    pre += Win_s[rl * 12 + c] * AUX[c];
                float hp = X0[grow];
                g_h1[g][t & 7][grow] =
                    0.5f * tanhf(pre) + 0.5f * hp + nse * hp * hp;
            }
            __syncthreads();
            if (tid == 0) redrel(c_h1);
        }
    } else if (loc < 10) {
        // ============================ B1: Wout @ h1 (off critical path) =====
        const int i1 = loc - 5;
        const int r0 = i1 * 100;
        unsigned* c_p1 = cb + 24 + 8 * i1;
        for (int i = tid; i < 51200; i += NTHR) {
            int r = i >> 9, k = i & 511;
            W[i] = (k < 500) ? Wout[(r0 + r) * 500 + k] : 0.f;
        }
        __syncthreads();

        for (int t = 0; t < TT; ++t) {
            if (tid == 0) {
                unsigned w1 = 5u * (unsigned)(t + 1);
                while (ldacq(c_h1) < w1) { }
            }
            __syncthreads();
            if (tid < 128)
                ((float4*)X0)[tid] =
                    __ldcg((const float4*)g_h1[g][t & 7] + tid);
            __syncthreads();

            float v = gemv100(Xv, Wv, rbase, lane);
            if (lane < nr)
                g_p1[g][t & 7][r0 + rbase + lane] = v;
            __syncthreads();
            if (tid == 0) redrel(c_p1);
        }
    } else if (loc < 15) {
        // ============================ B2: h2 recurrence =====================
        const int i2 = loc - 10;
        const int r0 = i2 * 100;
        unsigned* c_p1 = cb + 24 + 8 * i2;
        for (int i = tid; i < 51200; i += NTHR) {
            int r = i >> 9, k = i & 511;
            W[i] = (k < 500) ? Wsf2[(r0 + r) * 500 + k] : 0.f;
        }
        for (int i = tid; i < 100; i += NTHR) bias[i] = bout[r0 + i];
        __syncthreads();

        for (int t = 0; t < TT; ++t) {
            float nse = 0.f;
            if (t >= 1 && lane < nr)
                nse = n2g[(size_t)(t - 1) * 4500 + b * 500 + (r0 + rbase + lane)];

            if (tid == 0) {
                unsigned w1 = (unsigned)(t + 1);
                unsigned w2 = 5u * (unsigned)t;   // t=0: trivially satisfied
                for (;;) {
                    unsigned a = ldacq(c_p1);
                    unsigned c = ldacq(c_h2);
                    if (a >= w1 && c >= w2) break;
                }
            }
            __syncthreads();

            float par = 0.f;
            if (lane < nr)
                par = __ldcg(&g_p1[g][t & 7][r0 + rbase + lane]);
            if (tid < 128)
                ((float4*)X0)[tid] =
                    __ldcg((const float4*)g_h2[g][(t - 1) & 7] + tid);
            __syncthreads();

            float v = gemv100(Xv, Wv, rbase, lane);
            if (lane < nr) {
                int rl = rbase + lane, grow = r0 + rl;
                float pre = v + par + bias[rl];
                float val;
                if (t == 0) {
                    val = tanhf(pre);
                } else {
                    float hp = X0[grow];
                    val = 0.5f * tanhf(pre) + 0.5f * hp + nse * hp * hp;
                }
                g_h2[g][t & 7][grow] = val;
            }
            __syncthreads();
            if (tid == 0) redrel(c_h2);
        }
    } else {
        // ============================ C: muscles + arm ======================
        for (int i = tid; i < 6 * 512; i += NTHR) {
            int r = i >> 9, k = i & 511;
            W[i] = (k < 500) ? Wmus[r * 500 + k] : 0.f;
        }
        if (tid < 12) AUX[32 + tid] = Marm[tid];
        if (tid < 2)  AUX[48 + tid] = home[b * 2 + tid];
        __syncthreads();

        for (int t = 0; t < TT; ++t) {
            float nse = 0.f, pse = 0.f;
            if (t >= 1 && wrp == 0) {
                if (lane < 6) nse = nmg[(size_t)(t - 1) * 54 + b * 6 + lane];
                if (lane < 2) pse = pert[(size_t)(t - 1) * 18 + b * 2 + lane];
            }

            if (tid == 0) {
                unsigned w1 = 5u * (unsigned)(t + 1);
                while (ldacq(c_h2) < w1) { }
            }
            __syncthreads();
            if (tid < 128)
                ((float4*)X0)[tid] =
                    __ldcg((const float4*)g_h2[g][t & 7] + tid);
            __syncthreads();

            if (wrp == 0) {
                float acc[6];
                #pragma unroll
                for (int r = 0; r < 6; r++) acc[r] = 0.f;
                #pragma unroll
                for (int it = 0; it < 4; ++it) {
                    int ch = lane + 32 * it;
                    float4 x = Xv[ch];
                    #pragma unroll
                    for (int r = 0; r < 6; r++) {
                        float4 w = Wv[r * 128 + ch];
                        acc[r] += w.x * x.x + w.y * x.y + w.z * x.z + w.w * x.w;
                    }
                }
                bfly<6>(acc);
                float v = sel<6>(acc, lane);
                if (lane < 6) {
                    float dot = fmaxf(v, 0.f);
                    float mv;
                    if (t == 0) {
                        mv = dot;
                    } else {
                        float mp = AUX[8 + lane];
                        mv = 0.2f * dot + 0.8f * mp + nse * mp * mp;
                    }
                    AUX[8 + lane] = mv;
                    g_fb[g][t & 7][lane] = mv;
                }
                __syncwarp();
                if (lane < 2) {
                    int d = lane;
                    float pos, vel;
                    if (t == 0) {
                        pos = AUX[48 + d];
                        vel = 0.f;
                    } else {
                        float tq = pse;
                        #pragma unroll
                        for (int j = 0; j < 6; j++)
                            tq += AUX[8 + j] * AUX[32 + j * 2 + d];
                        vel = AUX[2 + d] + 0.01f * tq;
                        pos = AUX[0 + d] + 0.01f * vel;
                    }
                    AUX[0 + d] = pos;
                    AUX[2 + d] = vel;
                    out[t * 36 + b * 4 + d]     = pos;
                    out[t * 36 + b * 4 + 2 + d] = vel;
                    g_fb[g][t & 7][6 + d] = pos;
                    g_fb[g][t & 7][8 + d] = vel;
                }
            }
            __syncthreads();
            if (tid == 0) redrel(c_m);
        }
    }
}

extern "C" void kernel_launch(void* const* d_in, const int* in_sizes, int n_in,
                              void* d_out, int out_size) {
    // 0 des_targ (dead: scaled by 0), 1 perturb_seq, 2 noise_h1, 3 noise_h2,
    // 4 noise_m, 5 home, 6 W_in, 7 b_in, 8 W_in_self, 9 W_out, 10 b_out,
    // 11 W_out_self, 12 W_mus, 13 M_arm
    const float* pert = (const float*)d_in[1];
    const float* n1g  = (const float*)d_in[2];
    const float* n2g  = (const float*)d_in[3];
    const float* nmg  = (const float*)d_in[4];
    const float* home = (const float*)d_in[5];
    const float* Win  = (const float*)d_in[6];
    const float* bin  = (const float*)d_in[7];
    const float* Wsf1 = (const float*)d_in[8];
    const float* Wout = (const float*)d_in[9];
    const float* bout = (const float*)d_in[10];
    const float* Wsf2 = (const float*)d_in[11];
    const float* Wmus = (const float*)d_in[12];
    const float* Marm = (const float*)d_in[13];
    float* out = (float*)d_out;

    void *p;
    cudaGetSymbolAddress(&p, g_h1);  cudaMemsetAsync(p, 0, sizeof(g_h1),  0);
    cudaGetSymbolAddress(&p, g_h2);  cudaMemsetAsync(p, 0, sizeof(g_h2),  0);
    cudaGetSymbolAddress(&p, g_p1);  cudaMemsetAsync(p, 0, sizeof(g_p1),  0);
    cudaGetSymbolAddress(&p, g_fb);  cudaMemsetAsync(p, 0, sizeof(g_fb),  0);
    cudaGetSymbolAddress(&p, g_cnt); cudaMemsetAsync(p, 0, sizeof(g_cnt), 0);

    cudaFuncSetAttribute(ctrl_kernel,
                         cudaFuncAttributeMaxDynamicSharedMemorySize, SMEMB);

    ctrl_kernel<<<GRIDN, NTHR, SMEMB, 0>>>(pert, n1g, n2g, nmg, home,
                                           Win, bin, Wsf1, Wout, bout,
                                           Wsf2, Wmus, Marm, out);
}

// round 9
// speedup vs baseline: 2.0843x; 1.2093x over previous
#include <cuda_runtime.h>
#include <math.h>

#define TT     4096
#define NTHR   384
#define GRIDN  144            // 9 batches x (A:5, B1:5, B2:5, C:1)
#define SMEMB  212416

// depth-8 L2 rings, batch-partitioned
__device__ float    g_h1[9][8][512];
__device__ float    g_h2[9][8][512];
__device__ float    g_p1[9][8][512];   // B1 partials (Wout @ h1)
__device__ float    g_fb[9][8][16];    // m[0..5], pos[6..7], vel[8..9]
__device__ unsigned g_cnt[9 * 128];    // per batch: c_h1@0 c_h2@8 c_m@16 c_p1[i]@24+8i

__device__ __forceinline__ unsigned ldacq(const unsigned* p) {
    unsigned v;
    asm volatile("ld.acquire.gpu.global.u32 %0, [%1];" : "=r"(v) : "l"(p));
    return v;
}
__device__ __forceinline__ void redrel(unsigned* p) {
    asm volatile("red.release.gpu.global.add.u32 [%0], 1;" :: "l"(p));
}

template <int N>
__device__ __forceinline__ void bfly(float* a) {
    #pragma unroll
    for (int o = 16; o; o >>= 1)
        #pragma unroll
        for (int q = 0; q < N; q++) a[q] += __shfl_xor_sync(0xffffffffu, a[q], o);
}
template <int N>
__device__ __forceinline__ float sel(const float* a, int lane) {
    float v = 0.f;
    #pragma unroll
    for (int q = 0; q < N; q++) if (lane == q) v = a[q];
    return v;
}

__device__ __forceinline__ float dot4(float4 w, float4 x) {
    return w.x * x.x + w.y * x.y + w.z * x.z + w.w * x.w;
}

// 9-row GEMV, 3/4 of W in registers, chunk 3 from SMEM. X in registers (x0..x3).
__device__ __forceinline__ float gemv_rw(const float4 wreg[9][3], const float4* Wv,
                                         int rbase, int lane,
                                         float4 x0, float4 x1, float4 x2, float4 x3) {
    float acc[9];
    #pragma unroll
    for (int r = 0; r < 9; r++) {
        int rl = rbase + r; if (rl > 99) rl = 99;
        float4 w3 = Wv[rl * 128 + lane + 96];
        acc[r] = dot4(wreg[r][0], x0) + dot4(wreg[r][1], x1)
               + dot4(wreg[r][2], x2) + dot4(w3, x3);
    }
    bfly<9>(acc);
    return sel<9>(acc, lane);
}

__global__ void __launch_bounds__(NTHR, 1)
ctrl_kernel(const float* __restrict__ pert,
            const float* __restrict__ n1g,  const float* __restrict__ n2g,
            const float* __restrict__ nmg,  const float* __restrict__ home,
            const float* __restrict__ Win,  const float* __restrict__ bin,
            const float* __restrict__ Wsf1, const float* __restrict__ Wout,
            const float* __restrict__ bout, const float* __restrict__ Wsf2,
            const float* __restrict__ Wmus, const float* __restrict__ Marm,
            float* __restrict__ out)
{
    extern __shared__ float sm[];
    float* AUX   = sm;            // 64
    float* bias  = sm + 64;       // 128
    float* Win_s = sm + 192;      // 1200 (A only)
    float* W     = sm + 1392;     // 51200, 512 pitch

    const int tid  = threadIdx.x;
    const int lane = tid & 31;
    const int wrp  = tid >> 5;
    const int bid  = blockIdx.x;
    const int g    = bid >> 4;
    const int loc  = bid & 15;
    const int b    = g;

    unsigned* cb   = &g_cnt[g * 128];
    unsigned* c_h1 = cb;
    unsigned* c_h2 = cb + 8;
    unsigned* c_m  = cb + 16;

    const float4* Wv = (const float4*)W;
    const int rbase = (wrp * 100) / 12;
    const int nr    = ((wrp + 1) * 100) / 12 - rbase;
    const int grow0 = rbase + lane;            // finalized row (lane<nr)

    if (loc < 5) {
        // ============================ A: h1 =================================
        const int r0 = loc * 100;
        for (int i = tid; i < 51200; i += NTHR) {
            int r = i >> 9, k = i & 511;
            W[i] = (k < 500) ? Wsf1[(r0 + r) * 500 + k] : 0.f;
        }
        for (int i = tid; i < 1200; i += NTHR)
            Win_s[i] = Win[(r0 + i / 12) * 12 + (i % 12)];
        for (int i = tid; i < 100; i += NTHR) bias[i] = bin[r0 + i];
        if (tid < 2) AUX[32 + tid] = home[b * 2 + tid];
        __syncthreads();

        float4 wreg[9][3];
        #pragma unroll
        for (int r = 0; r < 9; r++) {
            int rl = rbase + r; if (rl > 99) rl = 99;
            #pragma unroll
            for (int c = 0; c < 3; c++)
                wreg[r][c] = Wv[rl * 128 + lane + 32 * c];
        }

        if (tid < 100) g_h1[g][0][r0 + tid] = tanhf(bias[tid]);   // h1(0)
        __syncthreads();
        if (tid == 0) redrel(c_h1);

        for (int t = 1; t < TT; ++t) {
            float nse = 0.f;
            if (lane < nr)
                nse = n1g[(size_t)(t - 1) * 4500 + b * 500 + (r0 + grow0)];

            if (tid == 0) {
                int tm = t - 6; if (tm < 0) tm = 0;
                unsigned w1 = 5u * (unsigned)t, w2 = (unsigned)(tm + 1);
                for (;;) {
                    unsigned a = ldacq(c_h1);
                    unsigned c = ldacq(c_m);
                    if (a >= w1 && c >= w2) break;
                }
            }
            __syncthreads();

            const float4* Xr = (const float4*)g_h1[g][(t - 1) & 7];
            float4 x0 = __ldcg(Xr + lane);
            float4 x1 = __ldcg(Xr + lane + 32);
            float4 x2 = __ldcg(Xr + lane + 64);
            float4 x3 = __ldcg(Xr + lane + 96);
            float hp = 0.f;
            if (lane < nr) hp = __ldcg(&g_h1[g][(t - 1) & 7][r0 + grow0]);
            if (tid < 12) {
                int c = tid;
                int t6 = t - 6; if (t6 < 0) t6 = 0;
                const float* fb = g_fb[g][t6 & 7];
                float v = 0.f;
                if (c >= 2 && c < 4)      v = 2.0f * (__ldcg(fb + 6 + (c - 2)) - AUX[32 + (c - 2)]);
                else if (c >= 4 && c < 6) v = 0.5f * __ldcg(fb + 8 + (c - 4));
                else if (c >= 6)          v = __ldcg(fb + (c - 6));
                AUX[c] = v;
            }

            float v = gemv_rw(wreg, Wv, rbase, lane, x0, x1, x2, x3);
            __syncthreads();                       // AUX ready for all

            if (lane < nr) {
                int rl = grow0;
                float pre = v + bias[rl];
                #pragma unroll
                for (int c = 0; c < 12; c++)
                    pre += Win_s[rl * 12 + c] * AUX[c];
                g_h1[g][t & 7][r0 + rl] =
                    0.5f * tanhf(pre) + 0.5f * hp + nse * hp * hp;
            }
            __syncthreads();
            if (tid == 0) redrel(c_h1);
        }
    } else if (loc < 10) {
        // ============================ B1: Wout @ h1 =========================
        const int i1 = loc - 5;
        const int r0 = i1 * 100;
        unsigned* c_p1 = cb + 24 + 8 * i1;
        for (int i = tid; i < 51200; i += NTHR) {
            int r = i >> 9, k = i & 511;
            W[i] = (k < 500) ? Wout[(r0 + r) * 500 + k] : 0.f;
        }
        __syncthreads();
        float4 wreg[9][3];
        #pragma unroll
        for (int r = 0; r < 9; r++) {
            int rl = rbase + r; if (rl > 99) rl = 99;
            #pragma unroll
            for (int c = 0; c < 3; c++)
                wreg[r][c] = Wv[rl * 128 + lane + 32 * c];
        }
        __syncthreads();

        for (int t = 0; t < TT; ++t) {
            if (tid == 0) {
                unsigned w1 = 5u * (unsigned)(t + 1);
                while (ldacq(c_h1) < w1) { }
            }
            __syncthreads();
            const float4* Xr = (const float4*)g_h1[g][t & 7];
            float4 x0 = __ldcg(Xr + lane);
            float4 x1 = __ldcg(Xr + lane + 32);
            float4 x2 = __ldcg(Xr + lane + 64);
            float4 x3 = __ldcg(Xr + lane + 96);

            float v = gemv_rw(wreg, Wv, rbase, lane, x0, x1, x2, x3);
            if (lane < nr)
                g_p1[g][t & 7][r0 + grow0] = v;
            __syncthreads();
            if (tid == 0) redrel(c_p1);
        }
    } else if (loc < 15) {
        // ============================ B2: h2 recurrence =====================
        const int i2 = loc - 10;
        const int r0 = i2 * 100;
        unsigned* c_p1 = cb + 24 + 8 * i2;
        for (int i = tid; i < 51200; i += NTHR) {
            int r = i >> 9, k = i & 511;
            W[i] = (k < 500) ? Wsf2[(r0 + r) * 500 + k] : 0.f;
        }
        for (int i = tid; i < 100; i += NTHR) bias[i] = bout[r0 + i];
        __syncthreads();
        float4 wreg[9][3];
        #pragma unroll
        for (int r = 0; r < 9; r++) {
            int rl = rbase + r; if (rl > 99) rl = 99;
            #pragma unroll
            for (int c = 0; c < 3; c++)
                wreg[r][c] = Wv[rl * 128 + lane + 32 * c];
        }
        __syncthreads();

        for (int t = 0; t < TT; ++t) {
            float nse = 0.f;
            if (t >= 1 && lane < nr)
                nse = n2g[(size_t)(t - 1) * 4500 + b * 500 + (r0 + grow0)];

            if (tid == 0) {
                unsigned w1 = (unsigned)(t + 1);
                unsigned w2 = 5u * (unsigned)t;
                for (;;) {
                    unsigned a = ldacq(c_p1);
                    unsigned c = ldacq(c_h2);
                    if (a >= w1 && c >= w2) break;
                }
            }
            __syncthreads();

            const float4* Xr = (const float4*)g_h2[g][(t - 1) & 7];
            float4 x0 = __ldcg(Xr + lane);
            float4 x1 = __ldcg(Xr + lane + 32);
            float4 x2 = __ldcg(Xr + lane + 64);
            float4 x3 = __ldcg(Xr + lane + 96);
            float par = 0.f, hp = 0.f;
            if (lane < nr) {
                par = __ldcg(&g_p1[g][t & 7][r0 + grow0]);
                hp  = __ldcg(&g_h2[g][(t - 1) & 7][r0 + grow0]);
            }

            float v = gemv_rw(wreg, Wv, rbase, lane, x0, x1, x2, x3);
            if (lane < nr) {
                float pre = v + par + bias[grow0];
                float val;
                if (t == 0) {
                    val = tanhf(pre);
                } else {
                    val = 0.5f * tanhf(pre) + 0.5f * hp + nse * hp * hp;
                }
                g_h2[g][t & 7][r0 + grow0] = val;
            }
            __syncthreads();
            if (tid == 0) redrel(c_h2);
        }
    } else {
        // ============================ C: muscles + arm ======================
        for (int i = tid; i < 6 * 512; i += NTHR) {
            int r = i >> 9, k = i & 511;
            W[i] = (k < 500) ? Wmus[r * 500 + k] : 0.f;
        }
        if (tid < 12) AUX[32 + tid] = Marm[tid];
        if (tid < 2)  AUX[48 + tid] = home[b * 2 + tid];
        __syncthreads();

        for (int t = 0; t < TT; ++t) {
            float nse = 0.f, pse = 0.f;
            if (t >= 1 && wrp == 0) {
                if (lane < 6) nse = nmg[(size_t)(t - 1) * 54 + b * 6 + lane];
                if (lane < 2) pse = pert[(size_t)(t - 1) * 18 + b * 2 + lane];
            }

            if (tid == 0) {
                unsigned w1 = 5u * (unsigned)(t + 1);
                while (ldacq(c_h2) < w1) { }
            }
            __syncthreads();

            if (wrp == 0) {
                const float4* Xr = (const float4*)g_h2[g][t & 7];
                float4 xs[4];
                #pragma unroll
                for (int it = 0; it < 4; ++it) xs[it] = __ldcg(Xr + lane + 32 * it);
                float acc[6];
                #pragma unroll
                for (int r = 0; r < 6; r++) acc[r] = 0.f;
                #pragma unroll
                for (int it = 0; it < 4; ++it) {
                    int ch = lane + 32 * it;
                    #pragma unroll
                    for (int r = 0; r < 6; r++)
                        acc[r] += dot4(Wv[r * 128 + ch], xs[it]);
                }
                bfly<6>(acc);
                float v = sel<6>(acc, lane);
                if (lane < 6) {
                    float dot = fmaxf(v, 0.f);
                    float mv;
                    if (t == 0) {
                        mv = dot;
                    } else {
                        float mp = AUX[8 + lane];
                        mv = 0.2f * dot + 0.8f * mp + nse * mp * mp;
                    }
                    AUX[8 + lane] = mv;
                    g_fb[g][t & 7][lane] = mv;
                }
                __syncwarp();
                if (lane < 2) {
                    int d = lane;
                    float pos, vel;
                    if (t == 0) {
                        pos = AUX[48 + d];
                        vel = 0.f;
                    } else {
                        float tq = pse;
                        #pragma unroll
                        for (int j = 0; j < 6; j++)
                            tq += AUX[8 + j] * AUX[32 + j * 2 + d];
                        vel = AUX[2 + d] + 0.01f * tq;
                        pos = AUX[0 + d] + 0.01f * vel;
                    }
                    AUX[0 + d] = pos;
                    AUX[2 + d] = vel;
                    out[t * 36 + b * 4 + d]     = pos;
                    out[t * 36 + b * 4 + 2 + d] = vel;
                    g_fb[g][t & 7][6 + d] = pos;
                    g_fb[g][t & 7][8 + d] = vel;
                }
            }
            __syncthreads();
            if (tid == 0) redrel(c_m);
        }
    }
}

extern "C" void kernel_launch(void* const* d_in, const int* in_sizes, int n_in,
                              void* d_out, int out_size) {
    // 0 des_targ (dead: scaled by 0), 1 perturb_seq, 2 noise_h1, 3 noise_h2,
    // 4 noise_m, 5 home, 6 W_in, 7 b_in, 8 W_in_self, 9 W_out, 10 b_out,
    // 11 W_out_self, 12 W_mus, 13 M_arm
    const float* pert = (const float*)d_in[1];
    const float* n1g  = (const float*)d_in[2];
    const float* n2g  = (const float*)d_in[3];
    const float* nmg  = (const float*)d_in[4];
    const float* home = (const float*)d_in[5];
    const float* Win  = (const float*)d_in[6];
    const float* bin  = (const float*)d_in[7];
    const float* Wsf1 = (const float*)d_in[8];
    const float* Wout = (const float*)d_in[9];
    const float* bout = (const float*)d_in[10];
    const float* Wsf2 = (const float*)d_in[11];
    const float* Wmus = (const float*)d_in[12];
    const float* Marm = (const float*)d_in[13];
    float* out = (float*)d_out;

    void *p;
    cudaGetSymbolAddress(&p, g_h1);  cudaMemsetAsync(p, 0, sizeof(g_h1),  0);
    cudaGetSymbolAddress(&p, g_h2);  cudaMemsetAsync(p, 0, sizeof(g_h2),  0);
    cudaGetSymbolAddress(&p, g_p1);  cudaMemsetAsync(p, 0, sizeof(g_p1),  0);
    cudaGetSymbolAddress(&p, g_fb);  cudaMemsetAsync(p, 0, sizeof(g_fb),  0);
    cudaGetSymbolAddress(&p, g_cnt); cudaMemsetAsync(p, 0, sizeof(g_cnt), 0);

    cudaFuncSetAttribute(ctrl_kernel,
                         cudaFuncAttributeMaxDynamicSharedMemorySize, SMEMB);

    ctrl_kernel<<<GRIDN, NTHR, SMEMB, 0>>>(pert, n1g, n2g, nmg, home,
                                           Win, bin, Wsf1, Wout, bout,
                                           Wsf2, Wmus, Marm, out);
}